// round 2
// baseline (speedup 1.0000x reference)
#include <cuda_runtime.h>
#include <cuda_fp16.h>

#define D      128
#define H0     64
#define W0     96
#define NPIX0  (H0*W0)        // 6144
#define NPIX_T 8160           // 6144+1536+384+96

__device__ float  g_f1 [NPIX_T * D];   // fp32 channel-last, all levels
__device__ float  g_f2f[NPIX0  * D];   // fp32 channel-last, level 0 only (pool source)
__device__ __half g_f2h[NPIX_T * D];   // fp16 channel-last, all levels (corr gather)
__device__ float  g_crd[NPIX_T * 2];

__constant__ int c_HL[4] = {64, 32, 16, 8};
__constant__ int c_WL[4] = {96, 48, 24, 12};
__constant__ int c_PO[4] = {0, 6144, 7680, 8064};
__constant__ int c_OO[4] = {0, 81*6144, 81*7680, 81*8064};

// ---------------------------------------------------------------------------
// Transpose (D, H*W) -> (H*W, D), level 0. f1 -> fp32; f2 -> fp32 + fp16.
// ---------------------------------------------------------------------------
__global__ void k_transpose(const float* __restrict__ f1, const float* __restrict__ f2) {
    __shared__ float tile[32][33];
    int z  = blockIdx.z;
    const float* src = z ? f2 : f1;
    int p0 = blockIdx.x * 32;
    int d0 = blockIdx.y * 32;
    #pragma unroll
    for (int i = 0; i < 4; i++)
        tile[threadIdx.y + 8*i][threadIdx.x] =
            src[(d0 + threadIdx.y + 8*i) * NPIX0 + p0 + threadIdx.x];
    __syncthreads();
    #pragma unroll
    for (int i = 0; i < 4; i++) {
        int p = p0 + threadIdx.y + 8*i;
        int d = d0 + threadIdx.x;
        float v = tile[threadIdx.x][threadIdx.y + 8*i];
        if (z) {
            g_f2f[(size_t)p * D + d] = v;
            g_f2h[(size_t)p * D + d] = __float2half(v);
        } else {
            g_f1[(size_t)p * D + d] = v;
        }
    }
}

// ---------------------------------------------------------------------------
// All pooled levels (1..3) for both maps, pooled DIRECTLY from level 0
// (mean of means == mean over the 2^l x 2^l window). fp32 accumulate.
// ---------------------------------------------------------------------------
#define POOL_N (2016 * D)  // pixels at levels 1..3 = 1536+384+96
__global__ void k_pool_all() {
    int idx = blockIdx.x * blockDim.x + threadIdx.x;
    if (idx >= 2 * POOL_N) return;
    int m = (idx >= POOL_N);                 // 0 = f1, 1 = f2
    int q = idx - m * POOL_N;
    int d  = q & (D - 1);
    int pl = q >> 7;                         // local pooled pixel 0..2015
    int l, pbase;
    if      (pl < 1536) { l = 1; pbase = 0;    }
    else if (pl < 1920) { l = 2; pbase = 1536; }
    else                { l = 3; pbase = 1920; }
    int pp = pl - pbase;
    int Wl = c_WL[l];
    int w  = pp % Wl, h = pp / Wl;
    int F  = 1 << l;
    const float* src = m ? g_f2f : g_f1;
    float acc = 0.f;
    for (int i = 0; i < F; i++)
        for (int j = 0; j < F; j++)
            acc += src[(size_t)((h*F + i) * W0 + (w*F + j)) * D + d];
    acc *= 1.0f / (F * F);
    size_t o = (size_t)(c_PO[l] + pp) * D + d;
    if (m) g_f2h[o] = __float2half(acc);
    else   g_f1 [o] = acc;
}

// ---------------------------------------------------------------------------
// Per-level coords (level 0 copy; levels 1-3 = jax.image.resize linear with
// antialias triangle kernel), then / 2^level.
// ---------------------------------------------------------------------------
__global__ void k_coords(const float* __restrict__ crd) {
    int p = blockIdx.x * blockDim.x + threadIdx.x;
    if (p >= NPIX_T) return;
    int l;
    if      (p >= 8064) l = 3;
    else if (p >= 7680) l = 2;
    else if (p >= 6144) l = 1;
    else                l = 0;
    int q  = p - c_PO[l];
    int Wl = c_WL[l];
    int h  = q / Wl, w = q % Wl;
    float gx, gy;
    if (l == 0) {
        gx = crd[q];
        gy = crd[NPIX0 + q];
    } else {
        float s  = (float)(1 << l);
        float cy = (h + 0.5f) * s - 0.5f;
        float cx = (w + 0.5f) * s - 0.5f;
        int jy0 = max(0,    (int)ceilf (cy - s));
        int jy1 = min(H0-1, (int)floorf(cy + s));
        int jx0 = max(0,    (int)ceilf (cx - s));
        int jx1 = min(W0-1, (int)floorf(cx + s));
        float sumy = 0.f, sumx = 0.f;
        for (int j = jy0; j <= jy1; j++) sumy += 1.f - fabsf(j - cy) / s;
        for (int i = jx0; i <= jx1; i++) sumx += 1.f - fabsf(i - cx) / s;
        float ax = 0.f, ay = 0.f;
        for (int j = jy0; j <= jy1; j++) {
            float wy = 1.f - fabsf(j - cy) / s;
            for (int i = jx0; i <= jx1; i++) {
                float wgt = wy * (1.f - fabsf(i - cx) / s);
                ax += wgt * crd[j * W0 + i];
                ay += wgt * crd[NPIX0 + j * W0 + i];
            }
        }
        float inv = 1.f / (sumx * sumy * s);
        gx = ax * inv;
        gy = ay * inv;
    }
    g_crd[p*2]   = gx;
    g_crd[p*2+1] = gy;
}

// ---------------------------------------------------------------------------
// Fused local correlation for ALL levels. 16 pixels per block, 256 threads.
// Phase 1: 100 window dots per pixel; one LDG.128 of fp16 f2 serves TWO
//          window positions (16 lanes each), 4-step shfl reduce.
// Phase 2: 81 bilinear combines per pixel with border clamping; coalesced
//          16-float stores.
// ---------------------------------------------------------------------------
#define TILE 16
__global__ void __launch_bounds__(256) k_corr_all(float* __restrict__ out) {
    int b = blockIdx.x;
    int l, tbase;
    if      (b < 384) { l = 0; tbase = 0;   }
    else if (b < 480) { l = 1; tbase = 384; }
    else if (b < 504) { l = 2; tbase = 480; }
    else              { l = 3; tbase = 504; }
    int Hl = c_HL[l], Wl = c_WL[l];
    int pixoff = c_PO[l];
    int HW = Hl * Wl;
    int pix0 = (b - tbase) * TILE;           // local pixel base within level

    int tid  = threadIdx.x;
    int lane = tid & 31, warp = tid >> 5;
    int lane16 = lane & 15, psel = lane >> 4;

    __shared__ __align__(16) float f1s[TILE * D];    // 8 KB
    __shared__ float gsh[TILE * 100];                // 6.4 KB
    __shared__ float cxs[TILE], cys[TILE], fxs[TILE], fys[TILE];
    __shared__ int   bxs[TILE], bys[TILE];

    // load f1 tile (coalesced float4)
    {
        const float4* src = (const float4*)(g_f1 + (size_t)(pixoff + pix0) * D);
        float4*       dst = (float4*)f1s;
        #pragma unroll
        for (int i = 0; i < (TILE * D / 4) / 256; i++)
            dst[tid + 256*i] = src[tid + 256*i];
    }
    if (tid < TILE) {
        float cx = g_crd[(pixoff + pix0 + tid) * 2];
        float cy = g_crd[(pixoff + pix0 + tid) * 2 + 1];
        cxs[tid] = cx; cys[tid] = cy;
        float fxx = floorf(cx), fyy = floorf(cy);
        bxs[tid] = (int)fxx; bys[tid] = (int)fyy;
        fxs[tid] = cx - fxx; fys[tid] = cy - fyy;
    }
    __syncthreads();

    // Phase 1: TILE*50 pair-tasks; each covers 2 window positions.
    const float4* f1s4 = (const float4*)f1s;
    for (int task = warp; task < TILE * 50; task += 8) {
        int pix = task / 50;
        int pp  = task - pix * 50;
        int pos = 2 * pp + psel;
        int u   = pos / 10;
        int t   = pos - u * 10;
        int px = min(max(bxs[pix] + t - 4, 0), Wl - 1);
        int py = min(max(bys[pix] + u - 4, 0), Hl - 1);
        const float4* row = (const float4*)(g_f2h + (size_t)(pixoff + py * Wl + px) * D);
        float4 hv = row[lane16];             // 8 halves = 16B
        __half2 h0 = ((const __half2*)&hv)[0];
        __half2 h1 = ((const __half2*)&hv)[1];
        __half2 h2 = ((const __half2*)&hv)[2];
        __half2 h3 = ((const __half2*)&hv)[3];
        float2 v0 = __half22float2(h0);
        float2 v1 = __half22float2(h1);
        float2 v2 = __half22float2(h2);
        float2 v3 = __half22float2(h3);
        float4 a0 = f1s4[pix * 32 + lane16 * 2];
        float4 a1 = f1s4[pix * 32 + lane16 * 2 + 1];
        float s = a0.x*v0.x + a0.y*v0.y + a0.z*v1.x + a0.w*v1.y
                + a1.x*v2.x + a1.y*v2.y + a1.z*v3.x + a1.w*v3.y;
        #pragma unroll
        for (int o = 8; o > 0; o >>= 1)
            s += __shfl_xor_sync(0xffffffffu, s, o);
        if (lane16 == 0) gsh[pix * 100 + pos] = s;
    }
    __syncthreads();

    // Phase 2: 81 * TILE outputs, coalesced over pixels.
    for (int idx = tid; idx < 81 * TILE; idx += 256) {
        int k = idx >> 4;          // 0..80
        int j = idx & (TILE - 1);  // pixel within tile
        int adx = k / 9;           // x-offset idx (slow)
        int bdy = k - adx * 9;     // y-offset idx (fast)
        int t0 = bxs[j] + adx - 4;
        int u0 = bys[j] + bdy - 4;
        float wx1 = (t0 < 0 || t0 >= Wl - 1) ? 0.f : fxs[j];
        float wy1 = (u0 < 0 || u0 >= Hl - 1) ? 0.f : fys[j];
        float wx0 = 1.f - wx1, wy0 = 1.f - wy1;
        const float* g = gsh + j * 100 + bdy * 10 + adx;
        float c = wy0 * (wx0 * g[0]  + wx1 * g[1])
                + wy1 * (wx0 * g[10] + wx1 * g[11]);
        out[c_OO[l] + k * HW + pix0 + j] = c * 0.08838834764831845f; // 1/sqrt(128)
    }
}

// ---------------------------------------------------------------------------
extern "C" void kernel_launch(void* const* d_in, const int* in_sizes, int n_in,
                              void* d_out, int out_size) {
    const float* f1  = (const float*)d_in[0];
    const float* f2  = (const float*)d_in[1];
    const float* crd = (const float*)d_in[2];
    float* out = (float*)d_out;

    dim3 tb(32, 8);
    k_transpose<<<dim3(NPIX0/32, D/32, 2), tb>>>(f1, f2);
    k_pool_all<<<(2 * POOL_N + 255) / 256, 256>>>();
    k_coords<<<(NPIX_T + 255) / 256, 256>>>(crd);
    k_corr_all<<<510, 256>>>(out);
}

// round 3
// speedup vs baseline: 3.3591x; 3.3591x over previous
#include <cuda_runtime.h>
#include <cuda_fp16.h>

#define D      128
#define H0     64
#define W0     96
#define NPIX0  (H0*W0)        // 6144
#define NPIX_T 8160           // 6144+1536+384+96

__device__ __align__(16) float  g_f1 [NPIX_T * D];   // fp32 channel-last, all levels
__device__ __align__(16) float  g_f2f[NPIX0  * D];   // fp32 channel-last, level 0 (pool src)
__device__ __align__(16) __half g_f2h[NPIX_T * D];   // fp16 channel-last, all levels
__device__ float  g_crd [NPIX_T * 2];
__device__ float  g_tmpA[5376 * 2];                  // x-resized coords, levels 1-3 (H0 rows)

__constant__ int c_HL[4] = {64, 32, 16, 8};
__constant__ int c_WL[4] = {96, 48, 24, 12};
__constant__ int c_PO[4] = {0, 6144, 7680, 8064};
__constant__ int c_OO[4] = {0, 81*6144, 81*7680, 81*8064};

// ---------------------------------------------------------------------------
// Transpose (D, H*W) -> (H*W, D), level 0. f1 -> fp32; f2 -> fp32 + fp16.
// ---------------------------------------------------------------------------
__global__ void k_transpose(const float* __restrict__ f1, const float* __restrict__ f2) {
    __shared__ float tile[32][33];
    int z  = blockIdx.z;
    const float* src = z ? f2 : f1;
    int p0 = blockIdx.x * 32;
    int d0 = blockIdx.y * 32;
    #pragma unroll
    for (int i = 0; i < 4; i++)
        tile[threadIdx.y + 8*i][threadIdx.x] =
            src[(d0 + threadIdx.y + 8*i) * NPIX0 + p0 + threadIdx.x];
    __syncthreads();
    #pragma unroll
    for (int i = 0; i < 4; i++) {
        int p = p0 + threadIdx.y + 8*i;
        int d = d0 + threadIdx.x;
        float v = tile[threadIdx.x][threadIdx.y + 8*i];
        if (z) {
            g_f2f[(size_t)p * D + d] = v;
            g_f2h[(size_t)p * D + d] = __float2half(v);
        } else {
            g_f1[(size_t)p * D + d] = v;
        }
    }
}

// ---------------------------------------------------------------------------
// All pooled levels (1..3), both maps, pooled directly from level 0.
// ---------------------------------------------------------------------------
#define POOL_N (2016 * D)
__global__ void k_pool_all() {
    int idx = blockIdx.x * blockDim.x + threadIdx.x;
    if (idx >= 2 * POOL_N) return;
    int m = (idx >= POOL_N);
    int q = idx - m * POOL_N;
    int d  = q & (D - 1);
    int pl = q >> 7;
    int l, pbase;
    if      (pl < 1536) { l = 1; pbase = 0;    }
    else if (pl < 1920) { l = 2; pbase = 1536; }
    else                { l = 3; pbase = 1920; }
    int pp = pl - pbase;
    int Wl = c_WL[l];
    int w  = pp % Wl, h = pp / Wl;
    int F  = 1 << l;
    const float* src = m ? g_f2f : g_f1;
    float acc = 0.f;
    for (int i = 0; i < F; i++)
        for (int j = 0; j < F; j++)
            acc += src[(size_t)((h*F + i) * W0 + (w*F + j)) * D + d];
    acc *= 1.0f / (F * F);
    size_t o = (size_t)(c_PO[l] + pp) * D + d;
    if (m) g_f2h[o] = __float2half(acc);
    else   g_f1 [o] = acc;
}

// ---------------------------------------------------------------------------
// Coords pass A: level-0 copy + x-axis triangle resize for levels 1-3
// (output rows still at full H0=64).  tmpA levels at offsets {0,3072,4608},
// widths {48,24,12}.
// ---------------------------------------------------------------------------
__global__ void k_coordsA(const float* __restrict__ crd) {
    int idx = blockIdx.x * blockDim.x + threadIdx.x;
    if (idx < 2 * NPIX0) {             // level-0 copy: g_crd[q*2+ax]
        int q = idx >> 1, ax = idx & 1;
        g_crd[idx] = crd[ax * NPIX0 + q];
        return;
    }
    idx -= 2 * NPIX0;
    if (idx >= 5376 * 2) return;
    int p = idx >> 1, ax = idx & 1;
    int l, base;
    if      (p < 3072) { l = 1; base = 0;    }
    else if (p < 4608) { l = 2; base = 3072; }
    else               { l = 3; base = 4608; }
    int q  = p - base;
    int Wl = c_WL[l];
    int h  = q / Wl, w = q % Wl;
    float s  = (float)(1 << l);
    float cxx = (w + 0.5f) * s - 0.5f;
    int j0 = max(0,    (int)ceilf (cxx - s));
    int j1 = min(W0-1, (int)floorf(cxx + s));
    float sum = 0.f, acc = 0.f;
    for (int i = j0; i <= j1; i++) {
        float wgt = 1.f - fabsf(i - cxx) / s;
        sum += wgt;
        acc += wgt * crd[ax * NPIX0 + h * W0 + i];
    }
    g_tmpA[p * 2 + ax] = acc / sum;
}

// ---------------------------------------------------------------------------
// Coords pass B: y-axis triangle resize for levels 1-3, then /2^l.
// ---------------------------------------------------------------------------
__global__ void k_coordsB() {
    int idx = blockIdx.x * blockDim.x + threadIdx.x;
    if (idx >= 2016 * 2) return;
    int p = idx >> 1, ax = idx & 1;
    int l, base, abase;
    if      (p < 1536) { l = 1; base = 0;    abase = 0;    }
    else if (p < 1920) { l = 2; base = 1536; abase = 3072; }
    else               { l = 3; base = 1920; abase = 4608; }
    int q  = p - base;
    int Wl = c_WL[l];
    int h  = q / Wl, w = q % Wl;
    float s  = (float)(1 << l);
    float cyy = (h + 0.5f) * s - 0.5f;
    int j0 = max(0,    (int)ceilf (cyy - s));
    int j1 = min(H0-1, (int)floorf(cyy + s));
    float sum = 0.f, acc = 0.f;
    for (int j = j0; j <= j1; j++) {
        float wgt = 1.f - fabsf(j - cyy) / s;
        sum += wgt;
        acc += wgt * g_tmpA[(abase + j * Wl + w) * 2 + ax];
    }
    g_crd[(c_PO[l] + q) * 2 + ax] = acc / (sum * s);
}

// ---------------------------------------------------------------------------
// Fused local correlation, all levels. 8 pixels/block, warp <-> pixel.
// f1 in registers; 100 window dots per warp over 25 iterations
// (2 positions per half-warp per iteration, 2 independent LDG + reduce
// chains for MLP). Phase 2: bilinear combine + coalesced stores.
// ---------------------------------------------------------------------------
#define TILE 8
__device__ __forceinline__ float dot8h(float4 a0, float4 a1, float4 hv) {
    const __half2* h = (const __half2*)&hv;
    float2 v0 = __half22float2(h[0]);
    float2 v1 = __half22float2(h[1]);
    float2 v2 = __half22float2(h[2]);
    float2 v3 = __half22float2(h[3]);
    return a0.x*v0.x + a0.y*v0.y + a0.z*v1.x + a0.w*v1.y
         + a1.x*v2.x + a1.y*v2.y + a1.z*v3.x + a1.w*v3.y;
}

__global__ void __launch_bounds__(256) k_corr_all(float* __restrict__ out) {
    int b = blockIdx.x;
    int l, tbase;
    if      (b < 768)  { l = 0; tbase = 0;    }
    else if (b < 960)  { l = 1; tbase = 768;  }
    else if (b < 1008) { l = 2; tbase = 960;  }
    else               { l = 3; tbase = 1008; }
    int Hl = c_HL[l], Wl = c_WL[l];
    int pixoff = c_PO[l];
    int HW = Hl * Wl;
    int pix0 = (b - tbase) * TILE;

    int tid  = threadIdx.x;
    int lane = tid & 31, warp = tid >> 5;
    int lane16 = lane & 15, psel = lane >> 4;

    __shared__ float gsh[TILE * 100];
    __shared__ float fxs[TILE], fys[TILE];
    __shared__ int   bxs[TILE], bys[TILE];

    int pix = pix0 + warp;                       // this warp's pixel (level-local)

    // f1 into registers (halves of warp read identical addresses -> broadcast)
    const float4* f1p = (const float4*)(g_f1 + (size_t)(pixoff + pix) * D);
    float4 a0 = f1p[lane16 * 2];
    float4 a1 = f1p[lane16 * 2 + 1];

    float cx = 0.f, cy = 0.f;
    if (lane == 0) {
        cx = g_crd[(pixoff + pix) * 2];
        cy = g_crd[(pixoff + pix) * 2 + 1];
    }
    cx = __shfl_sync(0xffffffffu, cx, 0);
    cy = __shfl_sync(0xffffffffu, cy, 0);
    float flx = floorf(cx), fly = floorf(cy);
    int bx = (int)flx, by = (int)fly;
    if (lane == 0) {
        bxs[warp] = bx; bys[warp] = by;
        fxs[warp] = cx - flx; fys[warp] = cy - fly;
    }

    const __half* f2l = g_f2h + (size_t)pixoff * D;

    #pragma unroll 5
    for (int i = 0; i < 25; i++) {
        int pA = i * 4 + psel * 2;               // 2 positions per half-warp
        int pB = pA + 1;
        int uA = (pA * 205) >> 11, tA = pA - uA * 10;
        int uB = (pB * 205) >> 11, tB = pB - uB * 10;
        int pxA = min(max(bx + tA - 4, 0), Wl - 1);
        int pyA = min(max(by + uA - 4, 0), Hl - 1);
        int pxB = min(max(bx + tB - 4, 0), Wl - 1);
        int pyB = min(max(by + uB - 4, 0), Hl - 1);
        const float4* rA = (const float4*)(f2l + (size_t)(pyA * Wl + pxA) * D);
        const float4* rB = (const float4*)(f2l + (size_t)(pyB * Wl + pxB) * D);
        float4 hA = rA[lane16];
        float4 hB = rB[lane16];
        float sA = dot8h(a0, a1, hA);
        float sB = dot8h(a0, a1, hB);
        #pragma unroll
        for (int o = 8; o > 0; o >>= 1) {
            sA += __shfl_xor_sync(0xffffffffu, sA, o);
            sB += __shfl_xor_sync(0xffffffffu, sB, o);
        }
        if (lane16 == 0) {
            gsh[warp * 100 + pA] = sA;
            gsh[warp * 100 + pB] = sB;
        }
    }
    __syncthreads();

    // Phase 2: 81*TILE outputs, coalesced over pixels.
    #pragma unroll
    for (int idx = tid; idx < 81 * TILE; idx += 256) {
        int k = idx >> 3;            // 0..80
        int j = idx & (TILE - 1);    // pixel within tile
        int adx = k / 9;             // x-offset idx (slow)
        int bdy = k - adx * 9;       // y-offset idx (fast)
        int t0 = bxs[j] + adx - 4;
        int u0 = bys[j] + bdy - 4;
        float wx1 = (t0 < 0 || t0 >= Wl - 1) ? 0.f : fxs[j];
        float wy1 = (u0 < 0 || u0 >= Hl - 1) ? 0.f : fys[j];
        float wx0 = 1.f - wx1, wy0 = 1.f - wy1;
        const float* g = gsh + j * 100 + bdy * 10 + adx;
        float c = wy0 * (wx0 * g[0]  + wx1 * g[1])
                + wy1 * (wx0 * g[10] + wx1 * g[11]);
        out[c_OO[l] + k * HW + pix0 + j] = c * 0.08838834764831845f; // 1/sqrt(128)
    }
}

// ---------------------------------------------------------------------------
extern "C" void kernel_launch(void* const* d_in, const int* in_sizes, int n_in,
                              void* d_out, int out_size) {
    const float* f1  = (const float*)d_in[0];
    const float* f2  = (const float*)d_in[1];
    const float* crd = (const float*)d_in[2];
    float* out = (float*)d_out;

    dim3 tb(32, 8);
    k_transpose<<<dim3(NPIX0/32, D/32, 2), tb>>>(f1, f2);
    k_pool_all<<<(2 * POOL_N + 255) / 256, 256>>>();
    k_coordsA<<<(2*NPIX0 + 5376*2 + 255) / 256, 256>>>(crd);
    k_coordsB<<<(2016*2 + 255) / 256, 256>>>();
    k_corr_all<<<1020, 256>>>(out);
}

// round 4
// speedup vs baseline: 3.8751x; 1.1536x over previous
#include <cuda_runtime.h>
#include <cuda_fp16.h>

#define D      128
#define H0     64
#define W0     96
#define NPIX0  (H0*W0)        // 6144
#define NPIX_T 8160           // 6144+1536+384+96

__device__ __align__(16) float  g_f1 [NPIX_T * D];   // fp32 channel-last, all levels
__device__ __align__(16) __half g_f2h[NPIX_T * D];   // fp16 channel-last, all levels
__device__ float  g_crd [NPIX_T * 2];
__device__ float  g_tmpA[5376 * 2];                  // x-resized coords, levels 1-3

__constant__ int c_HL[4] = {64, 32, 16, 8};
__constant__ int c_WL[4] = {96, 48, 24, 12};
__constant__ int c_PO[4] = {0, 6144, 7680, 8064};
__constant__ int c_OO[4] = {0, 81*6144, 81*7680, 81*8064};

// ---------------------------------------------------------------------------
// Kernel 1: transpose (D,HW)->(HW,D) for both maps (f1 fp32, f2 fp16)
//           + coordsA (level-0 coord copy + x-axis triangle resize) as extra
//           blocks, so the latency-bound coord work hides under the transpose.
// ---------------------------------------------------------------------------
#define TR_BLOCKS 1536          // 192 x 4 x 2
#define CA_ELEMS  (2*NPIX0 + 5376*2)   // 23040
#define CA_BLOCKS ((CA_ELEMS + 255)/256)

__global__ void __launch_bounds__(256) k_prep(const float* __restrict__ f1,
                                              const float* __restrict__ f2,
                                              const float* __restrict__ crd) {
    int b = blockIdx.x;
    if (b < TR_BLOCKS) {
        // ---- transpose ----
        __shared__ float tile[32][33];
        int bx = b % 192;
        int by = (b / 192) & 3;
        int z  = b / 768;
        const float* src = z ? f2 : f1;
        int p0 = bx * 32, d0 = by * 32;
        int tx = threadIdx.x & 31, ty = threadIdx.x >> 5;
        #pragma unroll
        for (int i = 0; i < 4; i++)
            tile[ty + 8*i][tx] = src[(d0 + ty + 8*i) * NPIX0 + p0 + tx];
        __syncthreads();
        #pragma unroll
        for (int i = 0; i < 4; i++) {
            int p = p0 + ty + 8*i;
            int d = d0 + tx;
            float v = tile[tx][ty + 8*i];
            if (z) g_f2h[(size_t)p * D + d] = __float2half(v);
            else   g_f1 [(size_t)p * D + d] = v;
        }
        return;
    }
    // ---- coordsA ----
    int idx = (b - TR_BLOCKS) * 256 + threadIdx.x;
    if (idx < 2 * NPIX0) {            // level-0: g_crd[q*2+ax] = crd[ax][q]
        int q = idx >> 1, ax = idx & 1;
        g_crd[idx] = crd[ax * NPIX0 + q];
        return;
    }
    idx -= 2 * NPIX0;
    if (idx >= 5376 * 2) return;
    int p = idx >> 1, ax = idx & 1;
    int l, base;
    if      (p < 3072) { l = 1; base = 0;    }
    else if (p < 4608) { l = 2; base = 3072; }
    else               { l = 3; base = 4608; }
    int q  = p - base;
    int Wl = c_WL[l];
    int h  = q / Wl, w = q % Wl;
    float s   = (float)(1 << l);
    float cxx = (w + 0.5f) * s - 0.5f;
    int j0 = max(0,    (int)ceilf (cxx - s));
    int j1 = min(W0-1, (int)floorf(cxx + s));
    float sum = 0.f, acc = 0.f;
    for (int i = j0; i <= j1; i++) {
        float wgt = 1.f - fabsf(i - cxx) / s;
        sum += wgt;
        acc += wgt * crd[ax * NPIX0 + h * W0 + i];
    }
    g_tmpA[p * 2 + ax] = acc / sum;
}

// ---------------------------------------------------------------------------
// Kernel 2: pooled levels 1..3 for both maps (f2 pooled from fp16 level 0,
//           fp32 accumulate) + coordsB (y-axis resize, /2^l) as extra blocks.
// ---------------------------------------------------------------------------
#define POOL_N   (2016 * D)
#define PL_BLOCKS ((2 * POOL_N) / 256)     // 2016
#define CB_ELEMS  (2016 * 2)

__global__ void __launch_bounds__(256) k_pool_coords() {
    int b = blockIdx.x;
    if (b < PL_BLOCKS) {
        int idx = b * 256 + threadIdx.x;
        int m = (idx >= POOL_N);
        int q = idx - m * POOL_N;
        int d  = q & (D - 1);
        int pl = q >> 7;
        int l, pbase;
        if      (pl < 1536) { l = 1; pbase = 0;    }
        else if (pl < 1920) { l = 2; pbase = 1536; }
        else                { l = 3; pbase = 1920; }
        int pp = pl - pbase;
        int Wl = c_WL[l];
        int w  = pp % Wl, h = pp / Wl;
        int F  = 1 << l;
        float acc = 0.f;
        if (m) {
            for (int i = 0; i < F; i++)
                for (int j = 0; j < F; j++)
                    acc += __half2float(g_f2h[(size_t)((h*F + i) * W0 + (w*F + j)) * D + d]);
        } else {
            for (int i = 0; i < F; i++)
                for (int j = 0; j < F; j++)
                    acc += g_f1[(size_t)((h*F + i) * W0 + (w*F + j)) * D + d];
        }
        acc *= 1.0f / (F * F);
        size_t o = (size_t)(c_PO[l] + pp) * D + d;
        if (m) g_f2h[o] = __float2half(acc);
        else   g_f1 [o] = acc;
        return;
    }
    // ---- coordsB ----
    int idx = (b - PL_BLOCKS) * 256 + threadIdx.x;
    if (idx >= CB_ELEMS) return;
    int p = idx >> 1, ax = idx & 1;
    int l, base, abase;
    if      (p < 1536) { l = 1; base = 0;    abase = 0;    }
    else if (p < 1920) { l = 2; base = 1536; abase = 3072; }
    else               { l = 3; base = 1920; abase = 4608; }
    int q  = p - base;
    int Wl = c_WL[l];
    int h  = q / Wl, w = q % Wl;
    float s   = (float)(1 << l);
    float cyy = (h + 0.5f) * s - 0.5f;
    int j0 = max(0,    (int)ceilf (cyy - s));
    int j1 = min(H0-1, (int)floorf(cyy + s));
    float sum = 0.f, acc = 0.f;
    for (int j = j0; j <= j1; j++) {
        float wgt = 1.f - fabsf(j - cyy) / s;
        sum += wgt;
        acc += wgt * g_tmpA[(abase + j * Wl + w) * 2 + ax];
    }
    g_crd[(c_PO[l] + q) * 2 + ax] = acc / (sum * s);
}

// ---------------------------------------------------------------------------
// Kernel 3: fused local correlation, all levels. 8 pixels/block, warp<->pixel,
// f1 in registers, 2 positions per half-warp per iteration.
// ---------------------------------------------------------------------------
#define TILE 8
__device__ __forceinline__ float dot8h(float4 a0, float4 a1, float4 hv) {
    const __half2* h = (const __half2*)&hv;
    float2 v0 = __half22float2(h[0]);
    float2 v1 = __half22float2(h[1]);
    float2 v2 = __half22float2(h[2]);
    float2 v3 = __half22float2(h[3]);
    return a0.x*v0.x + a0.y*v0.y + a0.z*v1.x + a0.w*v1.y
         + a1.x*v2.x + a1.y*v2.y + a1.z*v3.x + a1.w*v3.y;
}

__global__ void __launch_bounds__(256) k_corr_all(float* __restrict__ out) {
    int b = blockIdx.x;
    int l, tbase;
    if      (b < 768)  { l = 0; tbase = 0;    }
    else if (b < 960)  { l = 1; tbase = 768;  }
    else if (b < 1008) { l = 2; tbase = 960;  }
    else               { l = 3; tbase = 1008; }
    int Hl = c_HL[l], Wl = c_WL[l];
    int pixoff = c_PO[l];
    int HW = Hl * Wl;
    int pix0 = (b - tbase) * TILE;

    int tid  = threadIdx.x;
    int lane = tid & 31, warp = tid >> 5;
    int lane16 = lane & 15, psel = lane >> 4;

    __shared__ float gsh[TILE * 100];
    __shared__ float fxs[TILE], fys[TILE];
    __shared__ int   bxs[TILE], bys[TILE];

    int pix = pix0 + warp;

    const float4* f1p = (const float4*)(g_f1 + (size_t)(pixoff + pix) * D);
    float4 a0 = f1p[lane16 * 2];
    float4 a1 = f1p[lane16 * 2 + 1];

    float cx = 0.f, cy = 0.f;
    if (lane == 0) {
        cx = g_crd[(pixoff + pix) * 2];
        cy = g_crd[(pixoff + pix) * 2 + 1];
    }
    cx = __shfl_sync(0xffffffffu, cx, 0);
    cy = __shfl_sync(0xffffffffu, cy, 0);
    float flx = floorf(cx), fly = floorf(cy);
    int bx = (int)flx, by = (int)fly;
    if (lane == 0) {
        bxs[warp] = bx; bys[warp] = by;
        fxs[warp] = cx - flx; fys[warp] = cy - fly;
    }

    const __half* f2l = g_f2h + (size_t)pixoff * D;

    #pragma unroll 5
    for (int i = 0; i < 25; i++) {
        int pA = i * 4 + psel * 2;
        int pB = pA + 1;
        int uA = (pA * 205) >> 11, tA = pA - uA * 10;
        int uB = (pB * 205) >> 11, tB = pB - uB * 10;
        int pxA = min(max(bx + tA - 4, 0), Wl - 1);
        int pyA = min(max(by + uA - 4, 0), Hl - 1);
        int pxB = min(max(bx + tB - 4, 0), Wl - 1);
        int pyB = min(max(by + uB - 4, 0), Hl - 1);
        const float4* rA = (const float4*)(f2l + (size_t)(pyA * Wl + pxA) * D);
        const float4* rB = (const float4*)(f2l + (size_t)(pyB * Wl + pxB) * D);
        float4 hA = rA[lane16];
        float4 hB = rB[lane16];
        float sA = dot8h(a0, a1, hA);
        float sB = dot8h(a0, a1, hB);
        #pragma unroll
        for (int o = 8; o > 0; o >>= 1) {
            sA += __shfl_xor_sync(0xffffffffu, sA, o);
            sB += __shfl_xor_sync(0xffffffffu, sB, o);
        }
        if (lane16 == 0) {
            gsh[warp * 100 + pA] = sA;
            gsh[warp * 100 + pB] = sB;
        }
    }
    __syncthreads();

    #pragma unroll
    for (int idx = tid; idx < 81 * TILE; idx += 256) {
        int k = idx >> 3;
        int j = idx & (TILE - 1);
        int adx = k / 9;
        int bdy = k - adx * 9;
        int t0 = bxs[j] + adx - 4;
        int u0 = bys[j] + bdy - 4;
        float wx1 = (t0 < 0 || t0 >= Wl - 1) ? 0.f : fxs[j];
        float wy1 = (u0 < 0 || u0 >= Hl - 1) ? 0.f : fys[j];
        float wx0 = 1.f - wx1, wy0 = 1.f - wy1;
        const float* g = gsh + j * 100 + bdy * 10 + adx;
        float c = wy0 * (wx0 * g[0]  + wx1 * g[1])
                + wy1 * (wx0 * g[10] + wx1 * g[11]);
        out[c_OO[l] + k * HW + pix0 + j] = c * 0.08838834764831845f; // 1/sqrt(128)
    }
}

// ---------------------------------------------------------------------------
extern "C" void kernel_launch(void* const* d_in, const int* in_sizes, int n_in,
                              void* d_out, int out_size) {
    const float* f1  = (const float*)d_in[0];
    const float* f2  = (const float*)d_in[1];
    const float* crd = (const float*)d_in[2];
    float* out = (float*)d_out;

    k_prep<<<TR_BLOCKS + CA_BLOCKS, 256>>>(f1, f2, crd);
    k_pool_coords<<<PL_BLOCKS + (CB_ELEMS + 255)/256, 256>>>();
    k_corr_all<<<1020, 256>>>(out);
}

// round 5
// speedup vs baseline: 4.8029x; 1.2394x over previous
#include <cuda_runtime.h>
#include <cuda_fp16.h>

#define D      128
#define H0     64
#define W0     96
#define NPIX0  (H0*W0)        // 6144
#define NPIX_T 8160           // 6144+1536+384+96

__device__ __align__(16) float  g_f1 [NPIX_T * D];   // fp32 channel-last, all levels
__device__ __align__(16) __half g_f2h[NPIX_T * D];   // fp16 channel-last, all levels
__device__ float  g_crd [NPIX_T * 2];
__device__ float  g_tmpA[5376 * 2];                  // x-resized coords, levels 1-3

__constant__ int c_HL[4] = {64, 32, 16, 8};
__constant__ int c_WL[4] = {96, 48, 24, 12};
__constant__ int c_PO[4] = {0, 6144, 7680, 8064};
__constant__ int c_OO[4] = {0, 81*6144, 81*7680, 81*8064};

// ---------------------------------------------------------------------------
// Kernel 1: transpose (D,HW)->(HW,D) for both maps (f1 fp32, f2 fp16)
//           + coordsA (level-0 coord copy + x-axis triangle resize).
// ---------------------------------------------------------------------------
#define TR_BLOCKS 1536
#define CA_ELEMS  (2*NPIX0 + 5376*2)
#define CA_BLOCKS ((CA_ELEMS + 255)/256)

__global__ void __launch_bounds__(256) k_prep(const float* __restrict__ f1,
                                              const float* __restrict__ f2,
                                              const float* __restrict__ crd) {
    int b = blockIdx.x;
    if (b < TR_BLOCKS) {
        __shared__ float tile[32][33];
        int bx = b % 192;
        int by = (b / 192) & 3;
        int z  = b / 768;
        const float* src = z ? f2 : f1;
        int p0 = bx * 32, d0 = by * 32;
        int tx = threadIdx.x & 31, ty = threadIdx.x >> 5;
        #pragma unroll
        for (int i = 0; i < 4; i++)
            tile[ty + 8*i][tx] = src[(d0 + ty + 8*i) * NPIX0 + p0 + tx];
        __syncthreads();
        #pragma unroll
        for (int i = 0; i < 4; i++) {
            int p = p0 + ty + 8*i;
            int d = d0 + tx;
            float v = tile[tx][ty + 8*i];
            if (z) g_f2h[(size_t)p * D + d] = __float2half(v);
            else   g_f1 [(size_t)p * D + d] = v;
        }
        return;
    }
    int idx = (b - TR_BLOCKS) * 256 + threadIdx.x;
    if (idx < 2 * NPIX0) {
        int q = idx >> 1, ax = idx & 1;
        g_crd[idx] = crd[ax * NPIX0 + q];
        return;
    }
    idx -= 2 * NPIX0;
    if (idx >= 5376 * 2) return;
    int p = idx >> 1, ax = idx & 1;
    int l, base;
    if      (p < 3072) { l = 1; base = 0;    }
    else if (p < 4608) { l = 2; base = 3072; }
    else               { l = 3; base = 4608; }
    int q  = p - base;
    int Wl = c_WL[l];
    int h  = q / Wl, w = q % Wl;
    float s   = (float)(1 << l);
    float cxx = (w + 0.5f) * s - 0.5f;
    int j0 = max(0,    (int)ceilf (cxx - s));
    int j1 = min(W0-1, (int)floorf(cxx + s));
    float sum = 0.f, acc = 0.f;
    for (int i = j0; i <= j1; i++) {
        float wgt = 1.f - fabsf(i - cxx) / s;
        sum += wgt;
        acc += wgt * crd[ax * NPIX0 + h * W0 + i];
    }
    g_tmpA[p * 2 + ax] = acc / sum;
}

// ---------------------------------------------------------------------------
// Kernel 2: pooled levels 1..3 (per-level compile-time-unrolled taps -> high
//           MLP) + coordsB (y-axis resize, /2^l).
// ---------------------------------------------------------------------------
#define POOL_N   (2016 * D)
#define PL_BLOCKS ((2 * POOL_N) / 256)
#define CB_ELEMS  (2016 * 2)

template<int F>
__device__ __forceinline__ float pool_f1(int h, int w, int d) {
    float acc = 0.f;
    #pragma unroll
    for (int i = 0; i < F; i++)
        #pragma unroll
        for (int j = 0; j < F; j++)
            acc += g_f1[(size_t)((h*F + i) * W0 + (w*F + j)) * D + d];
    return acc * (1.0f / (F * F));
}
template<int F>
__device__ __forceinline__ float pool_f2(int h, int w, int d) {
    float acc = 0.f;
    #pragma unroll
    for (int i = 0; i < F; i++)
        #pragma unroll
        for (int j = 0; j < F; j++)
            acc += __half2float(g_f2h[(size_t)((h*F + i) * W0 + (w*F + j)) * D + d]);
    return acc * (1.0f / (F * F));
}

__global__ void __launch_bounds__(256) k_pool_coords() {
    int b = blockIdx.x;
    if (b < PL_BLOCKS) {
        int idx = b * 256 + threadIdx.x;
        int m = (idx >= POOL_N);
        int q = idx - m * POOL_N;
        int d  = q & (D - 1);
        int pl = q >> 7;
        int l, pbase;
        if      (pl < 1536) { l = 1; pbase = 0;    }
        else if (pl < 1920) { l = 2; pbase = 1536; }
        else                { l = 3; pbase = 1920; }
        int pp = pl - pbase;
        int Wl = c_WL[l];
        int w  = pp % Wl, h = pp / Wl;
        float acc;
        if (m) {
            if      (l == 1) acc = pool_f2<2>(h, w, d);
            else if (l == 2) acc = pool_f2<4>(h, w, d);
            else             acc = pool_f2<8>(h, w, d);
            g_f2h[(size_t)(c_PO[l] + pp) * D + d] = __float2half(acc);
        } else {
            if      (l == 1) acc = pool_f1<2>(h, w, d);
            else if (l == 2) acc = pool_f1<4>(h, w, d);
            else             acc = pool_f1<8>(h, w, d);
            g_f1[(size_t)(c_PO[l] + pp) * D + d] = acc;
        }
        return;
    }
    int idx = (b - PL_BLOCKS) * 256 + threadIdx.x;
    if (idx >= CB_ELEMS) return;
    int p = idx >> 1, ax = idx & 1;
    int l, base, abase;
    if      (p < 1536) { l = 1; base = 0;    abase = 0;    }
    else if (p < 1920) { l = 2; base = 1536; abase = 3072; }
    else               { l = 3; base = 1920; abase = 4608; }
    int q  = p - base;
    int Wl = c_WL[l];
    int h  = q / Wl, w = q % Wl;
    float s   = (float)(1 << l);
    float cyy = (h + 0.5f) * s - 0.5f;
    int j0 = max(0,    (int)ceilf (cyy - s));
    int j1 = min(H0-1, (int)floorf(cyy + s));
    float sum = 0.f, acc = 0.f;
    for (int j = j0; j <= j1; j++) {
        float wgt = 1.f - fabsf(j - cyy) / s;
        sum += wgt;
        acc += wgt * g_tmpA[(abase + j * Wl + w) * 2 + ax];
    }
    g_crd[(c_PO[l] + q) * 2 + ax] = acc / (sum * s);
}

// ---------------------------------------------------------------------------
// Kernel 3: fused local correlation. Warp <-> pixel; 8-lane dot groups:
// each lane covers 16 channels, 4 positions per warp-iteration, 3-step
// shfl reduce serving all 4 positions at once.
// ---------------------------------------------------------------------------
#define TILE 8
__device__ __forceinline__ float dot8h(float4 a0, float4 a1, float4 hv) {
    const __half2* h = (const __half2*)&hv;
    float2 v0 = __half22float2(h[0]);
    float2 v1 = __half22float2(h[1]);
    float2 v2 = __half22float2(h[2]);
    float2 v3 = __half22float2(h[3]);
    return a0.x*v0.x + a0.y*v0.y + a0.z*v1.x + a0.w*v1.y
         + a1.x*v2.x + a1.y*v2.y + a1.z*v3.x + a1.w*v3.y;
}

__global__ void __launch_bounds__(256) k_corr_all(float* __restrict__ out) {
    int b = blockIdx.x;
    int l, tbase;
    if      (b < 768)  { l = 0; tbase = 0;    }
    else if (b < 960)  { l = 1; tbase = 768;  }
    else if (b < 1008) { l = 2; tbase = 960;  }
    else               { l = 3; tbase = 1008; }
    int Hl = c_HL[l], Wl = c_WL[l];
    int pixoff = c_PO[l];
    int HW = Hl * Wl;
    int pix0 = (b - tbase) * TILE;

    int tid   = threadIdx.x;
    int lane  = tid & 31, warp = tid >> 5;
    int lane8 = lane & 7, grp = lane >> 3;   // 4 groups of 8 lanes

    __shared__ float gsh[TILE * 100];
    __shared__ float fxs[TILE], fys[TILE];
    __shared__ int   bxs[TILE], bys[TILE];

    int pix = pix0 + warp;

    // f1 channels for this lane: [lane8*8, +8) and [64+lane8*8, +8)
    const float4* f1p = (const float4*)(g_f1 + (size_t)(pixoff + pix) * D);
    float4 a0 = f1p[lane8 * 2];
    float4 a1 = f1p[lane8 * 2 + 1];
    float4 a2 = f1p[16 + lane8 * 2];
    float4 a3 = f1p[16 + lane8 * 2 + 1];

    float cx = 0.f, cy = 0.f;
    if (lane == 0) {
        cx = g_crd[(pixoff + pix) * 2];
        cy = g_crd[(pixoff + pix) * 2 + 1];
    }
    cx = __shfl_sync(0xffffffffu, cx, 0);
    cy = __shfl_sync(0xffffffffu, cy, 0);
    float flx = floorf(cx), fly = floorf(cy);
    int bx = (int)flx, by = (int)fly;
    if (lane == 0) {
        bxs[warp] = bx; bys[warp] = by;
        fxs[warp] = cx - flx; fys[warp] = cy - fly;
    }

    const __half* f2l = g_f2h + (size_t)pixoff * D;

    #pragma unroll 5
    for (int i = 0; i < 25; i++) {
        int pos = i * 4 + grp;
        int u = (pos * 205) >> 11;       // pos / 10  (y index)
        int t = pos - u * 10;            // pos % 10  (x index)
        int px = min(max(bx + t - 4, 0), Wl - 1);
        int py = min(max(by + u - 4, 0), Hl - 1);
        const __half* row = f2l + (size_t)(py * Wl + px) * D;
        float4 h0 = *(const float4*)(row + lane8 * 8);
        float4 h1 = *(const float4*)(row + 64 + lane8 * 8);
        float s = dot8h(a0, a1, h0) + dot8h(a2, a3, h1);
        s += __shfl_xor_sync(0xffffffffu, s, 4);
        s += __shfl_xor_sync(0xffffffffu, s, 2);
        s += __shfl_xor_sync(0xffffffffu, s, 1);
        if (lane8 == 0) gsh[warp * 100 + pos] = s;
    }
    __syncthreads();

    #pragma unroll
    for (int idx = tid; idx < 81 * TILE; idx += 256) {
        int k = idx >> 3;
        int j = idx & (TILE - 1);
        int adx = k / 9;
        int bdy = k - adx * 9;
        int t0 = bxs[j] + adx - 4;
        int u0 = bys[j] + bdy - 4;
        float wx1 = (t0 < 0 || t0 >= Wl - 1) ? 0.f : fxs[j];
        float wy1 = (u0 < 0 || u0 >= Hl - 1) ? 0.f : fys[j];
        float wx0 = 1.f - wx1, wy0 = 1.f - wy1;
        const float* g = gsh + j * 100 + bdy * 10 + adx;
        float c = wy0 * (wx0 * g[0]  + wx1 * g[1])
                + wy1 * (wx0 * g[10] + wx1 * g[11]);
        out[c_OO[l] + k * HW + pix0 + j] = c * 0.08838834764831845f; // 1/sqrt(128)
    }
}

// ---------------------------------------------------------------------------
extern "C" void kernel_launch(void* const* d_in, const int* in_sizes, int n_in,
                              void* d_out, int out_size) {
    const float* f1  = (const float*)d_in[0];
    const float* f2  = (const float*)d_in[1];
    const float* crd = (const float*)d_in[2];
    float* out = (float*)d_out;

    k_prep<<<TR_BLOCKS + CA_BLOCKS, 256>>>(f1, f2, crd);
    k_pool_coords<<<PL_BLOCKS + (CB_ELEMS + 255)/256, 256>>>();
    k_corr_all<<<1020, 256>>>(out);
}